// round 12
// baseline (speedup 1.0000x reference)
#include <cuda_runtime.h>
#include <cuda_bf16.h>
#include <cstdint>

// ---------------------------------------------------------------------------
// GCNDeep: 4-layer GCN
//   per layer: support = act(h) @ W ; agg = b + segment_sum(w * support[src], dst)
// Strategy:
//   - Build dst-binned CSR once per launch (histogram -> scan -> place).
//     Edge metadata packed as int2 {src, bitcast(weight)} for single-LDG.64 access.
//   - Per layer: SIMT fp32 GEMM using packed fma.rn.f32x2 (2 FMA lanes/issue,
//     B300-only via PTX). W transposed in smem so both operands are k-paired.
//   - Atomic-free warp-per-node gather-aggregate with bias folded in and
//     ReLU applied by the next GEMM's tile stage.
// ---------------------------------------------------------------------------

#define N_NODES_MAX 50000
#define N_EDGES_MAX 800000
#define FEAT 128

__device__ float g_bufA[N_NODES_MAX * FEAT];   // h / agg
__device__ float g_bufB[N_NODES_MAX * FEAT];   // support
__device__ int   g_counts[N_NODES_MAX];        // per-dst degree
__device__ int   g_rowptr[N_NODES_MAX + 1];    // CSR row pointers
__device__ int   g_pos[N_NODES_MAX];           // placement cursors
__device__ int2  g_edge_p[N_EDGES_MAX];        // {src, bitcast(w)} permuted into dst bins

// ---------------------------------------------------------------------------
// CSR build
// ---------------------------------------------------------------------------
__global__ void hist_kernel(const int* __restrict__ dst, int* __restrict__ counts, int E)
{
    int i = blockIdx.x * blockDim.x + threadIdx.x;
    if (i < E) atomicAdd(&counts[dst[i]], 1);
}

// Single-block exclusive scan over counts[0..n) -> row_ptr (and pos copy).
__global__ void __launch_bounds__(1024) scan_kernel(
    const int* __restrict__ counts, int* __restrict__ row_ptr,
    int* __restrict__ pos, int n)
{
    __shared__ int warp_sums[32];
    __shared__ int carry_s;
    if (threadIdx.x == 0) carry_s = 0;
    __syncthreads();

    const int lane = threadIdx.x & 31;
    const int wid  = threadIdx.x >> 5;

    for (int base = 0; base < n; base += 1024) {
        int i = base + (int)threadIdx.x;
        int v = (i < n) ? counts[i] : 0;
        int s = v;
#pragma unroll
        for (int o = 1; o < 32; o <<= 1) {
            int t = __shfl_up_sync(0xffffffffu, s, o);
            if (lane >= o) s += t;
        }
        if (lane == 31) warp_sums[wid] = s;
        __syncthreads();
        if (wid == 0) {
            int ws = warp_sums[lane];
#pragma unroll
            for (int o = 1; o < 32; o <<= 1) {
                int t = __shfl_up_sync(0xffffffffu, ws, o);
                if (lane >= o) ws += t;
            }
            warp_sums[lane] = ws;
        }
        __syncthreads();
        int incl = s + (wid > 0 ? warp_sums[wid - 1] : 0) + carry_s;
        int excl = incl - v;
        if (i < n) { row_ptr[i] = excl; pos[i] = excl; }
        __syncthreads();
        if (threadIdx.x == 1023) carry_s = incl;
        __syncthreads();
    }
    if (threadIdx.x == 0) row_ptr[n] = carry_s;
}

__global__ void place_kernel(
    const int* __restrict__ src, const int* __restrict__ dst,
    const float* __restrict__ ew, int* __restrict__ pos,
    int2* __restrict__ edge_p, int E)
{
    int i = blockIdx.x * blockDim.x + threadIdx.x;
    if (i >= E) return;
    int p = atomicAdd(&pos[dst[i]], 1);
    edge_p[p] = make_int2(src[i], __float_as_int(ew[i]));
}

// ---------------------------------------------------------------------------
// Packed f32x2 FMA (B300: 2 fp32 FMA lanes per issue; PTX-only instruction)
// ---------------------------------------------------------------------------
__device__ __forceinline__ void fma_f32x2(unsigned long long& d,
                                          unsigned long long a,
                                          unsigned long long b) {
    asm("fma.rn.f32x2 %0, %1, %2, %0;" : "+l"(d) : "l"(a), "l"(b));
}

// ---------------------------------------------------------------------------
// GEMM: out[M, NOUT] tile = act(X[M,128]) @ W[128, NOUT], split along N.
// Block = BM=128 rows x BN=64 cols, 512 threads, 2 CTAs/SM.
// W is transposed into smem (Ws_t[c][k], stride 132) so both operands load
// as k-adjacent float2 pairs; inner loop is pure LDS.64 + fma.rn.f32x2.
// Per-thread tile: 4 rows x 4 cols, cols strided by 16 (conflict-free Ws_t).
// acc[r][j] holds even/odd-k partial sums; horizontal add at epilogue.
// ---------------------------------------------------------------------------
template <bool RELU>
__global__ void __launch_bounds__(512, 2) gemm_kernel(
    const float* __restrict__ X, const float* __restrict__ W,
    float* __restrict__ out, int M, int NOUT)
{
    constexpr int BM = 128;
    constexpr int BN = 64;
    constexpr int XS = FEAT + 4;       // padded X row stride (floats)
    constexpr int WT = FEAT + 4;       // padded Ws_t row stride (floats)

    extern __shared__ float smem[];
    float* Wt = smem;                  // [BN][WT]  (transposed W half)
    float* Xs = smem + BN * WT;        // [BM][XS]

    const int tid  = threadIdx.x;
    const int row0 = blockIdx.x * BM;
    const int c0   = blockIdx.y * BN;

    // Stage W half transposed: Wt[c][k] = W[k][c0+c]
    // Read coalesced float4 along N, scatter 4 scalars into Wt columns.
    for (int i = tid; i < FEAT * BN / 4; i += 512) {
        int k  = i >> 4;               // 0..127
        int cg4 = (i & 15) * 4;        // col group base
        float4 v = *(const float4*)(W + (size_t)k * NOUT + c0 + cg4);
        Wt[(cg4 + 0) * WT + k] = v.x;
        Wt[(cg4 + 1) * WT + k] = v.y;
        Wt[(cg4 + 2) * WT + k] = v.z;
        Wt[(cg4 + 3) * WT + k] = v.w;
    }

    // Stage X tile: 128 rows x 128 cols (32 float4 per row), optional ReLU
    for (int i = tid; i < BM * FEAT / 4; i += 512) {
        int r = i >> 5;                // row
        int k = (i & 31) * 4;          // col
        int grow = row0 + r;
        float4 v = make_float4(0.f, 0.f, 0.f, 0.f);
        if (grow < M) v = *(const float4*)(X + (size_t)grow * FEAT + k);
        if (RELU) {
            v.x = fmaxf(v.x, 0.f); v.y = fmaxf(v.y, 0.f);
            v.z = fmaxf(v.z, 0.f); v.w = fmaxf(v.w, 0.f);
        }
        *(float4*)(Xs + r * XS + k) = v;
    }
    __syncthreads();

    const int cg    = tid & 15;        // col base; thread cols = cg + 16j
    const int rg    = tid >> 4;        // 32 row-groups
    const int rbase = rg * 4;          // 4 rows per thread

    unsigned long long acc[4][4];      // [row][colpair] f32x2 (even-k, odd-k)
#pragma unroll
    for (int r = 0; r < 4; r++)
#pragma unroll
        for (int j = 0; j < 4; j++) acc[r][j] = 0ull;

#pragma unroll 8
    for (int k0 = 0; k0 < FEAT; k0 += 2) {
        unsigned long long xv[4], wv[4];
#pragma unroll
        for (int r = 0; r < 4; r++)
            xv[r] = *(const unsigned long long*)(Xs + (rbase + r) * XS + k0);
#pragma unroll
        for (int j = 0; j < 4; j++)
            wv[j] = *(const unsigned long long*)(Wt + (cg + 16 * j) * WT + k0);
#pragma unroll
        for (int r = 0; r < 4; r++)
#pragma unroll
            for (int j = 0; j < 4; j++)
                fma_f32x2(acc[r][j], xv[r], wv[j]);
    }

#pragma unroll
    for (int r = 0; r < 4; r++) {
        int grow = row0 + rbase + r;
        if (grow < M) {
#pragma unroll
            for (int j = 0; j < 4; j++) {
                unsigned int lo = (unsigned int)(acc[r][j] & 0xffffffffull);
                unsigned int hi = (unsigned int)(acc[r][j] >> 32);
                float v = __uint_as_float(lo) + __uint_as_float(hi);
                out[(size_t)grow * NOUT + c0 + cg + 16 * j] = v;
            }
        }
    }
}

// ---------------------------------------------------------------------------
// Aggregate: one warp per dst node; acc = bias + sum_e w_e * support[src_e].
// Packed edge metadata loaded 32-at-a-time cooperatively (one LDG.64/lane),
// broadcast via shuffle. Two independent accumulators (even/odd edges)
// guarantee >=2 gathers in flight per warp regardless of ptxas scheduling.
// ---------------------------------------------------------------------------
template <int COLS>
__global__ void __launch_bounds__(256) aggregate_kernel(
    const float* __restrict__ support, const int* __restrict__ row_ptr,
    const int2* __restrict__ edge_p,
    const float* __restrict__ bias, float* __restrict__ out, int M)
{
    int warp = (blockIdx.x * blockDim.x + threadIdx.x) >> 5;
    int lane = threadIdx.x & 31;
    if (warp >= M) return;

    const int beg = row_ptr[warp];
    const int end = row_ptr[warp + 1];

    if (COLS == 128) {
        float4 acc0 = ((const float4*)bias)[lane];
        float4 acc1 = make_float4(0.f, 0.f, 0.f, 0.f);
        for (int e = beg; e < end; e += 32) {
            int n = min(32, end - e);
            int s = 0, wbits = 0;
            if (lane < n) {
                int2 m = __ldg(edge_p + e + lane);
                s = m.x; wbits = m.y;
            }
            int j = 0;
#pragma unroll 2
            for (; j + 1 < n; j += 2) {
                int   s0 = __shfl_sync(0xffffffffu, s, j);
                float w0 = __int_as_float(__shfl_sync(0xffffffffu, wbits, j));
                int   s1 = __shfl_sync(0xffffffffu, s, j + 1);
                float w1 = __int_as_float(__shfl_sync(0xffffffffu, wbits, j + 1));
                float4 v0 = ((const float4*)(support + (size_t)s0 * 128))[lane];
                float4 v1 = ((const float4*)(support + (size_t)s1 * 128))[lane];
                acc0.x += w0 * v0.x; acc0.y += w0 * v0.y;
                acc0.z += w0 * v0.z; acc0.w += w0 * v0.w;
                acc1.x += w1 * v1.x; acc1.y += w1 * v1.y;
                acc1.z += w1 * v1.z; acc1.w += w1 * v1.w;
            }
            if (j < n) {
                int   sj = __shfl_sync(0xffffffffu, s, j);
                float wj = __int_as_float(__shfl_sync(0xffffffffu, wbits, j));
                float4 v = ((const float4*)(support + (size_t)sj * 128))[lane];
                acc0.x += wj * v.x; acc0.y += wj * v.y;
                acc0.z += wj * v.z; acc0.w += wj * v.w;
            }
        }
        acc0.x += acc1.x; acc0.y += acc1.y; acc0.z += acc1.z; acc0.w += acc1.w;
        ((float4*)(out + (size_t)warp * 128))[lane] = acc0;
    } else {  // COLS == 64
        float2 acc0 = ((const float2*)bias)[lane];
        float2 acc1 = make_float2(0.f, 0.f);
        for (int e = beg; e < end; e += 32) {
            int n = min(32, end - e);
            int s = 0, wbits = 0;
            if (lane < n) {
                int2 m = __ldg(edge_p + e + lane);
                s = m.x; wbits = m.y;
            }
            int j = 0;
#pragma unroll 2
            for (; j + 1 < n; j += 2) {
                int   s0 = __shfl_sync(0xffffffffu, s, j);
                float w0 = __int_as_float(__shfl_sync(0xffffffffu, wbits, j));
                int   s1 = __shfl_sync(0xffffffffu, s, j + 1);
                float w1 = __int_as_float(__shfl_sync(0xffffffffu, wbits, j + 1));
                float2 v0 = ((const float2*)(support + (size_t)s0 * 64))[lane];
                float2 v1 = ((const float2*)(support + (size_t)s1 * 64))[lane];
                acc0.x += w0 * v0.x; acc0.y += w0 * v0.y;
                acc1.x += w1 * v1.x; acc1.y += w1 * v1.y;
            }
            if (j < n) {
                int   sj = __shfl_sync(0xffffffffu, s, j);
                float wj = __int_as_float(__shfl_sync(0xffffffffu, wbits, j));
                float2 v = ((const float2*)(support + (size_t)sj * 64))[lane];
                acc0.x += wj * v.x; acc0.y += wj * v.y;
            }
        }
        acc0.x += acc1.x; acc0.y += acc1.y;
        ((float2*)(out + (size_t)warp * 64))[lane] = acc0;
    }
}

// ---------------------------------------------------------------------------
// Launch
// ---------------------------------------------------------------------------
static inline int cdiv(int a, int b) { return (a + b - 1) / b; }

extern "C" void kernel_launch(void* const* d_in, const int* in_sizes, int n_in,
                              void* d_out, int out_size)
{
    const float* x    = (const float*)d_in[0];
    const int*   esrc = (const int*)  d_in[1];
    const int*   edst = (const int*)  d_in[2];
    const float* ew   = (const float*)d_in[3];
    const float* W0   = (const float*)d_in[4];
    const float* b0   = (const float*)d_in[5];
    const float* W1   = (const float*)d_in[6];
    const float* b1   = (const float*)d_in[7];
    const float* W2   = (const float*)d_in[8];
    const float* b2   = (const float*)d_in[9];
    const float* W3   = (const float*)d_in[10];
    const float* b3   = (const float*)d_in[11];
    float*       out  = (float*)d_out;

    const int M = in_sizes[0] / FEAT;   // 50000
    const int E = in_sizes[1];          // 800000

    float *bufA, *bufB;
    int *counts, *rowptr, *pos;
    int2 *edge_p;
    cudaGetSymbolAddress((void**)&bufA,   g_bufA);
    cudaGetSymbolAddress((void**)&bufB,   g_bufB);
    cudaGetSymbolAddress((void**)&counts, g_counts);
    cudaGetSymbolAddress((void**)&rowptr, g_rowptr);
    cudaGetSymbolAddress((void**)&pos,    g_pos);
    cudaGetSymbolAddress((void**)&edge_p, g_edge_p);

    // GEMM smem: Wt 64x132 + Xs 128x132 floats = 101376 bytes
    const int gemm_smem = (64 * (FEAT + 4) + 128 * (FEAT + 4)) * sizeof(float);
    cudaFuncSetAttribute(gemm_kernel<false>,
                         cudaFuncAttributeMaxDynamicSharedMemorySize, gemm_smem);
    cudaFuncSetAttribute(gemm_kernel<true>,
                         cudaFuncAttributeMaxDynamicSharedMemorySize, gemm_smem);

    const dim3 gemm128_grid(cdiv(M, 128), 2);   // two 64-wide N-halves
    const dim3 gemm64_grid (cdiv(M, 128), 1);   // single 64-wide N
    const int  agg_blocks = cdiv(M * 32, 256);  // warp per node, 8 warps/block
    const int  e_blocks   = cdiv(E, 256);

    // ---- CSR build (once; reused by all 4 layers) ----
    cudaMemsetAsync(counts, 0, M * sizeof(int));
    hist_kernel<<<e_blocks, 256>>>(edst, counts, E);
    scan_kernel<<<1, 1024>>>(counts, rowptr, pos, M);
    place_kernel<<<e_blocks, 256>>>(esrc, edst, ew, pos, edge_p, E);

    // ---- Layer 0 ----
    gemm_kernel<false><<<gemm128_grid, 512, gemm_smem>>>(x, W0, bufB, M, 128);
    aggregate_kernel<128><<<agg_blocks, 256>>>(bufB, rowptr, edge_p, b0, bufA, M);

    // ---- Layer 1 ----
    gemm_kernel<true><<<gemm128_grid, 512, gemm_smem>>>(bufA, W1, bufB, M, 128);
    aggregate_kernel<128><<<agg_blocks, 256>>>(bufB, rowptr, edge_p, b1, bufA, M);

    // ---- Layer 2 ----
    gemm_kernel<true><<<gemm128_grid, 512, gemm_smem>>>(bufA, W2, bufB, M, 128);
    aggregate_kernel<128><<<agg_blocks, 256>>>(bufB, rowptr, edge_p, b2, bufA, M);

    // ---- Layer 3 (NOUT=64, no relu on output, straight into d_out) ----
    gemm_kernel<true><<<gemm64_grid, 512, gemm_smem>>>(bufA, W3, bufB, M, 64);
    aggregate_kernel<64><<<agg_blocks, 256>>>(bufB, rowptr, edge_p, b3, out, M);
}

// round 13
// speedup vs baseline: 1.0428x; 1.0428x over previous
#include <cuda_runtime.h>
#include <cuda_bf16.h>
#include <cstdint>

// ---------------------------------------------------------------------------
// GCNDeep: 4-layer GCN
//   per layer: support = act(h) @ W ; agg = b + segment_sum(w * support[src], dst)
// Strategy:
//   - Build dst-binned CSR once per launch (histogram -> scan -> place).
//     Edge metadata packed as int2 {src, bitcast(weight)} for single-LDG.64 access.
//   - Per layer: SIMT fp32 GEMM (BM=128 x BN=64 tiles, 512 thr, ~50% occ),
//     then atomic-free warp-per-node gather-aggregate (4 gathers in flight)
//     with bias folded in and ReLU applied by the next GEMM's tile stage.
// ---------------------------------------------------------------------------

#define N_NODES_MAX 50000
#define N_EDGES_MAX 800000
#define FEAT 128

__device__ float g_bufA[N_NODES_MAX * FEAT];   // h / agg
__device__ float g_bufB[N_NODES_MAX * FEAT];   // support
__device__ int   g_counts[N_NODES_MAX];        // per-dst degree
__device__ int   g_rowptr[N_NODES_MAX + 1];    // CSR row pointers
__device__ int   g_pos[N_NODES_MAX];           // placement cursors
__device__ int2  g_edge_p[N_EDGES_MAX];        // {src, bitcast(w)} permuted into dst bins

// ---------------------------------------------------------------------------
// CSR build
// ---------------------------------------------------------------------------
__global__ void hist_kernel(const int* __restrict__ dst, int* __restrict__ counts, int E)
{
    int i = blockIdx.x * blockDim.x + threadIdx.x;
    if (i < E) atomicAdd(&counts[dst[i]], 1);
}

// Single-block exclusive scan over counts[0..n) -> row_ptr (and pos copy).
__global__ void __launch_bounds__(1024) scan_kernel(
    const int* __restrict__ counts, int* __restrict__ row_ptr,
    int* __restrict__ pos, int n)
{
    __shared__ int warp_sums[32];
    __shared__ int carry_s;
    if (threadIdx.x == 0) carry_s = 0;
    __syncthreads();

    const int lane = threadIdx.x & 31;
    const int wid  = threadIdx.x >> 5;

    for (int base = 0; base < n; base += 1024) {
        int i = base + (int)threadIdx.x;
        int v = (i < n) ? counts[i] : 0;
        int s = v;
#pragma unroll
        for (int o = 1; o < 32; o <<= 1) {
            int t = __shfl_up_sync(0xffffffffu, s, o);
            if (lane >= o) s += t;
        }
        if (lane == 31) warp_sums[wid] = s;
        __syncthreads();
        if (wid == 0) {
            int ws = warp_sums[lane];
#pragma unroll
            for (int o = 1; o < 32; o <<= 1) {
                int t = __shfl_up_sync(0xffffffffu, ws, o);
                if (lane >= o) ws += t;
            }
            warp_sums[lane] = ws;
        }
        __syncthreads();
        int incl = s + (wid > 0 ? warp_sums[wid - 1] : 0) + carry_s;
        int excl = incl - v;
        if (i < n) { row_ptr[i] = excl; pos[i] = excl; }
        __syncthreads();
        if (threadIdx.x == 1023) carry_s = incl;
        __syncthreads();
    }
    if (threadIdx.x == 0) row_ptr[n] = carry_s;
}

__global__ void place_kernel(
    const int* __restrict__ src, const int* __restrict__ dst,
    const float* __restrict__ ew, int* __restrict__ pos,
    int2* __restrict__ edge_p, int E)
{
    int i = blockIdx.x * blockDim.x + threadIdx.x;
    if (i >= E) return;
    int p = atomicAdd(&pos[dst[i]], 1);
    edge_p[p] = make_int2(src[i], __float_as_int(ew[i]));
}

// ---------------------------------------------------------------------------
// GEMM: out[M, NOUT] tile = act(X[M,128]) @ W[128, NOUT], split along N.
// Block = BM=128 rows x BN=64 cols, 512 threads, 2 CTAs/SM (98KB smem) ->
// 32 warps/SM. Per-thread 4x4 register tile; per 4-k chunk:
// 8 LDS.128 vs 64 FFMA. blockIdx.y selects the 64-wide N-half.
// (R10-measured: 56.9us, fma 46.1% ~= 92% of FFMA rt=2 issue ceiling.)
// ---------------------------------------------------------------------------
template <bool RELU>
__global__ void __launch_bounds__(512, 2) gemm_kernel(
    const float* __restrict__ X, const float* __restrict__ W,
    float* __restrict__ out, int M, int NOUT)
{
    constexpr int BM = 128;
    constexpr int BN = 64;
    constexpr int XS = FEAT + 4;       // padded X row stride (floats)

    extern __shared__ float smem[];
    float* Ws = smem;                  // [128][64]
    float* Xs = smem + FEAT * BN;      // [BM][XS]

    const int tid  = threadIdx.x;
    const int row0 = blockIdx.x * BM;
    const int c0   = blockIdx.y * BN;

    // Stage W half: 128 rows x 64 cols (16 float4 per row)
    for (int i = tid; i < FEAT * BN / 4; i += 512) {
        int k = i >> 4;                // row
        int c = (i & 15) * 4;          // col within half
        *(float4*)(Ws + k * BN + c) = *(const float4*)(W + (size_t)k * NOUT + c0 + c);
    }

    // Stage X tile: 128 rows x 128 cols (32 float4 per row), optional ReLU
    for (int i = tid; i < BM * FEAT / 4; i += 512) {
        int r = i >> 5;                // row
        int k = (i & 31) * 4;          // col
        int grow = row0 + r;
        float4 v = make_float4(0.f, 0.f, 0.f, 0.f);
        if (grow < M) v = *(const float4*)(X + (size_t)grow * FEAT + k);
        if (RELU) {
            v.x = fmaxf(v.x, 0.f); v.y = fmaxf(v.y, 0.f);
            v.z = fmaxf(v.z, 0.f); v.w = fmaxf(v.w, 0.f);
        }
        *(float4*)(Xs + r * XS + k) = v;
    }
    __syncthreads();

    const int cg    = tid & 15;        // 16 col-groups x 4 cols
    const int rg    = tid >> 4;        // 32 row-groups
    const int rbase = rg * 4;          // 4 rows per thread

    float acc[4][4];
#pragma unroll
    for (int r = 0; r < 4; r++)
#pragma unroll
        for (int c = 0; c < 4; c++) acc[r][c] = 0.f;

#pragma unroll 4
    for (int k0 = 0; k0 < FEAT; k0 += 4) {
        float4 wv[4];
#pragma unroll
        for (int j = 0; j < 4; j++)
            wv[j] = *(float4*)(Ws + (k0 + j) * BN + cg * 4);
        float4 xv[4];
#pragma unroll
        for (int r = 0; r < 4; r++)
            xv[r] = *(float4*)(Xs + (rbase + r) * XS + k0);
#pragma unroll
        for (int r = 0; r < 4; r++) {
#pragma unroll
            for (int c = 0; c < 4; c++) {
                acc[r][c] += xv[r].x * (&wv[0].x)[c] + xv[r].y * (&wv[1].x)[c]
                           + xv[r].z * (&wv[2].x)[c] + xv[r].w * (&wv[3].x)[c];
            }
        }
    }

#pragma unroll
    for (int r = 0; r < 4; r++) {
        int grow = row0 + rbase + r;
        if (grow < M) {
            float4 v = make_float4(acc[r][0], acc[r][1], acc[r][2], acc[r][3]);
            *(float4*)(out + (size_t)grow * NOUT + c0 + cg * 4) = v;
        }
    }
}

// ---------------------------------------------------------------------------
// Aggregate: one warp per dst node; acc = bias + sum_e w_e * support[src_e].
// Packed edge metadata loaded 32-at-a-time cooperatively (one LDG.64/lane),
// broadcast via shuffle. FOUR independent accumulators keep >=4 gathers in
// flight per warp (L2-hit lat ~234cyc is the binding constraint).
// ---------------------------------------------------------------------------
template <int COLS>
__global__ void __launch_bounds__(256) aggregate_kernel(
    const float* __restrict__ support, const int* __restrict__ row_ptr,
    const int2* __restrict__ edge_p,
    const float* __restrict__ bias, float* __restrict__ out, int M)
{
    int warp = (blockIdx.x * blockDim.x + threadIdx.x) >> 5;
    int lane = threadIdx.x & 31;
    if (warp >= M) return;

    const int beg = row_ptr[warp];
    const int end = row_ptr[warp + 1];

    if (COLS == 128) {
        float4 acc0 = ((const float4*)bias)[lane];
        float4 acc1 = make_float4(0.f, 0.f, 0.f, 0.f);
        float4 acc2 = make_float4(0.f, 0.f, 0.f, 0.f);
        float4 acc3 = make_float4(0.f, 0.f, 0.f, 0.f);
        for (int e = beg; e < end; e += 32) {
            int n = min(32, end - e);
            int s = 0, wbits = 0;
            if (lane < n) {
                int2 m = __ldg(edge_p + e + lane);
                s = m.x; wbits = m.y;
            }
            int j = 0;
            for (; j + 3 < n; j += 4) {
                int   s0 = __shfl_sync(0xffffffffu, s, j);
                float w0 = __int_as_float(__shfl_sync(0xffffffffu, wbits, j));
                int   s1 = __shfl_sync(0xffffffffu, s, j + 1);
                float w1 = __int_as_float(__shfl_sync(0xffffffffu, wbits, j + 1));
                int   s2 = __shfl_sync(0xffffffffu, s, j + 2);
                float w2 = __int_as_float(__shfl_sync(0xffffffffu, wbits, j + 2));
                int   s3 = __shfl_sync(0xffffffffu, s, j + 3);
                float w3 = __int_as_float(__shfl_sync(0xffffffffu, wbits, j + 3));
                float4 v0 = ((const float4*)(support + (size_t)s0 * 128))[lane];
                float4 v1 = ((const float4*)(support + (size_t)s1 * 128))[lane];
                float4 v2 = ((const float4*)(support + (size_t)s2 * 128))[lane];
                float4 v3 = ((const float4*)(support + (size_t)s3 * 128))[lane];
                acc0.x += w0 * v0.x; acc0.y += w0 * v0.y;
                acc0.z += w0 * v0.z; acc0.w += w0 * v0.w;
                acc1.x += w1 * v1.x; acc1.y += w1 * v1.y;
                acc1.z += w1 * v1.z; acc1.w += w1 * v1.w;
                acc2.x += w2 * v2.x; acc2.y += w2 * v2.y;
                acc2.z += w2 * v2.z; acc2.w += w2 * v2.w;
                acc3.x += w3 * v3.x; acc3.y += w3 * v3.y;
                acc3.z += w3 * v3.z; acc3.w += w3 * v3.w;
            }
            for (; j < n; j++) {
                int   sj = __shfl_sync(0xffffffffu, s, j);
                float wj = __int_as_float(__shfl_sync(0xffffffffu, wbits, j));
                float4 v = ((const float4*)(support + (size_t)sj * 128))[lane];
                acc0.x += wj * v.x; acc0.y += wj * v.y;
                acc0.z += wj * v.z; acc0.w += wj * v.w;
            }
        }
        acc0.x += acc1.x + acc2.x + acc3.x;
        acc0.y += acc1.y + acc2.y + acc3.y;
        acc0.z += acc1.z + acc2.z + acc3.z;
        acc0.w += acc1.w + acc2.w + acc3.w;
        ((float4*)(out + (size_t)warp * 128))[lane] = acc0;
    } else {  // COLS == 64
        float2 acc0 = ((const float2*)bias)[lane];
        float2 acc1 = make_float2(0.f, 0.f);
        float2 acc2 = make_float2(0.f, 0.f);
        float2 acc3 = make_float2(0.f, 0.f);
        for (int e = beg; e < end; e += 32) {
            int n = min(32, end - e);
            int s = 0, wbits = 0;
            if (lane < n) {
                int2 m = __ldg(edge_p + e + lane);
                s = m.x; wbits = m.y;
            }
            int j = 0;
            for (; j + 3 < n; j += 4) {
                int   s0 = __shfl_sync(0xffffffffu, s, j);
                float w0 = __int_as_float(__shfl_sync(0xffffffffu, wbits, j));
                int   s1 = __shfl_sync(0xffffffffu, s, j + 1);
                float w1 = __int_as_float(__shfl_sync(0xffffffffu, wbits, j + 1));
                int   s2 = __shfl_sync(0xffffffffu, s, j + 2);
                float w2 = __int_as_float(__shfl_sync(0xffffffffu, wbits, j + 2));
                int   s3 = __shfl_sync(0xffffffffu, s, j + 3);
                float w3 = __int_as_float(__shfl_sync(0xffffffffu, wbits, j + 3));
                float2 v0 = ((const float2*)(support + (size_t)s0 * 64))[lane];
                float2 v1 = ((const float2*)(support + (size_t)s1 * 64))[lane];
                float2 v2 = ((const float2*)(support + (size_t)s2 * 64))[lane];
                float2 v3 = ((const float2*)(support + (size_t)s3 * 64))[lane];
                acc0.x += w0 * v0.x; acc0.y += w0 * v0.y;
                acc1.x += w1 * v1.x; acc1.y += w1 * v1.y;
                acc2.x += w2 * v2.x; acc2.y += w2 * v2.y;
                acc3.x += w3 * v3.x; acc3.y += w3 * v3.y;
            }
            for (; j < n; j++) {
                int   sj = __shfl_sync(0xffffffffu, s, j);
                float wj = __int_as_float(__shfl_sync(0xffffffffu, wbits, j));
                float2 v = ((const float2*)(support + (size_t)sj * 64))[lane];
                acc0.x += wj * v.x; acc0.y += wj * v.y;
            }
        }
        acc0.x += acc1.x + acc2.x + acc3.x;
        acc0.y += acc1.y + acc2.y + acc3.y;
        ((float2*)(out + (size_t)warp * 64))[lane] = acc0;
    }
}

// ---------------------------------------------------------------------------
// Launch
// ---------------------------------------------------------------------------
static inline int cdiv(int a, int b) { return (a + b - 1) / b; }

extern "C" void kernel_launch(void* const* d_in, const int* in_sizes, int n_in,
                              void* d_out, int out_size)
{
    const float* x    = (const float*)d_in[0];
    const int*   esrc = (const int*)  d_in[1];
    const int*   edst = (const int*)  d_in[2];
    const float* ew   = (const float*)d_in[3];
    const float* W0   = (const float*)d_in[4];
    const float* b0   = (const float*)d_in[5];
    const float* W1   = (const float*)d_in[6];
    const float* b1   = (const float*)d_in[7];
    const float* W2   = (const float*)d_in[8];
    const float* b2   = (const float*)d_in[9];
    const float* W3   = (const float*)d_in[10];
    const float* b3   = (const float*)d_in[11];
    float*       out  = (float*)d_out;

    const int M = in_sizes[0] / FEAT;   // 50000
    const int E = in_sizes[1];          // 800000

    float *bufA, *bufB;
    int *counts, *rowptr, *pos;
    int2 *edge_p;
    cudaGetSymbolAddress((void**)&bufA,   g_bufA);
    cudaGetSymbolAddress((void**)&bufB,   g_bufB);
    cudaGetSymbolAddress((void**)&counts, g_counts);
    cudaGetSymbolAddress((void**)&rowptr, g_rowptr);
    cudaGetSymbolAddress((void**)&pos,    g_pos);
    cudaGetSymbolAddress((void**)&edge_p, g_edge_p);

    // GEMM smem: Ws 128x64 + Xs 128x132 floats = 100352 bytes
    const int gemm_smem = (FEAT * 64 + 128 * (FEAT + 4)) * sizeof(float);
    cudaFuncSetAttribute(gemm_kernel<false>,
                         cudaFuncAttributeMaxDynamicSharedMemorySize, gemm_smem);
    cudaFuncSetAttribute(gemm_kernel<true>,
                         cudaFuncAttributeMaxDynamicSharedMemorySize, gemm_smem);

    const dim3 gemm128_grid(cdiv(M, 128), 2);   // two 64-wide N-halves
    const dim3 gemm64_grid (cdiv(M, 128), 1);   // single 64-wide N
    const int  agg_blocks = cdiv(M * 32, 256);  // warp per node, 8 warps/block
    const int  e_blocks   = cdiv(E, 256);

    // ---- CSR build (once; reused by all 4 layers) ----
    cudaMemsetAsync(counts, 0, M * sizeof(int));
    hist_kernel<<<e_blocks, 256>>>(edst, counts, E);
    scan_kernel<<<1, 1024>>>(counts, rowptr, pos, M);
    place_kernel<<<e_blocks, 256>>>(esrc, edst, ew, pos, edge_p, E);

    // ---- Layer 0 ----
    gemm_kernel<false><<<gemm128_grid, 512, gemm_smem>>>(x, W0, bufB, M, 128);
    aggregate_kernel<128><<<agg_blocks, 256>>>(bufB, rowptr, edge_p, b0, bufA, M);

    // ---- Layer 1 ----
    gemm_kernel<true><<<gemm128_grid, 512, gemm_smem>>>(bufA, W1, bufB, M, 128);
    aggregate_kernel<128><<<agg_blocks, 256>>>(bufB, rowptr, edge_p, b1, bufA, M);

    // ---- Layer 2 ----
    gemm_kernel<true><<<gemm128_grid, 512, gemm_smem>>>(bufA, W2, bufB, M, 128);
    aggregate_kernel<128><<<agg_blocks, 256>>>(bufB, rowptr, edge_p, b2, bufA, M);

    // ---- Layer 3 (NOUT=64, no relu on output, straight into d_out) ----
    gemm_kernel<true><<<gemm64_grid, 512, gemm_smem>>>(bufA, W3, bufB, M, 64);
    aggregate_kernel<64><<<agg_blocks, 256>>>(bufB, rowptr, edge_p, b3, out, M);
}

// round 17
// speedup vs baseline: 1.1849x; 1.1362x over previous
#include <cuda_runtime.h>
#include <cuda_bf16.h>
#include <cstdint>

// ---------------------------------------------------------------------------
// GCNDeep: 4-layer GCN
//   per layer: support = act(h) @ W ; agg = b + segment_sum(w * support[src], dst)
// Strategy:
//   - CSR built once (hist -> scan -> place), packed int2 edge metadata.
//   - GEMM on tensor cores via warp-level mma.sync m16n8k16 bf16 (baseline
//     PTX, compiles for .target sm_103): split-bf16 (hi+lo), 3 products,
//     fp32 accumulation => ~1e-5 relative accuracy.
//   - Atomic-free warp-per-node gather-aggregate (2 gathers in flight; at the
//     chip LTS cap), bias folded in, ReLU applied at next GEMM's A staging.
// ---------------------------------------------------------------------------

#define N_NODES_MAX 50000
#define N_EDGES_MAX 800000
#define FEAT 128

__device__ float g_bufA[N_NODES_MAX * FEAT];   // h / agg
__device__ float g_bufB[N_NODES_MAX * FEAT];   // support
__device__ int   g_counts[N_NODES_MAX];
__device__ int   g_rowptr[N_NODES_MAX + 1];
__device__ int   g_pos[N_NODES_MAX];
__device__ int2  g_edge_p[N_EDGES_MAX];

// ---------------------------------------------------------------------------
// CSR build
// ---------------------------------------------------------------------------
__global__ void hist_kernel(const int* __restrict__ dst, int* __restrict__ counts, int E)
{
    int i = blockIdx.x * blockDim.x + threadIdx.x;
    if (i < E) atomicAdd(&counts[dst[i]], 1);
}

__global__ void __launch_bounds__(1024) scan_kernel(
    const int* __restrict__ counts, int* __restrict__ row_ptr,
    int* __restrict__ pos, int n)
{
    __shared__ int warp_sums[32];
    __shared__ int carry_s;
    if (threadIdx.x == 0) carry_s = 0;
    __syncthreads();

    const int lane = threadIdx.x & 31;
    const int wid  = threadIdx.x >> 5;

    for (int base = 0; base < n; base += 1024) {
        int i = base + (int)threadIdx.x;
        int v = (i < n) ? counts[i] : 0;
        int s = v;
#pragma unroll
        for (int o = 1; o < 32; o <<= 1) {
            int t = __shfl_up_sync(0xffffffffu, s, o);
            if (lane >= o) s += t;
        }
        if (lane == 31) warp_sums[wid] = s;
        __syncthreads();
        if (wid == 0) {
            int ws = warp_sums[lane];
#pragma unroll
            for (int o = 1; o < 32; o <<= 1) {
                int t = __shfl_up_sync(0xffffffffu, ws, o);
                if (lane >= o) ws += t;
            }
            warp_sums[lane] = ws;
        }
        __syncthreads();
        int incl = s + (wid > 0 ? warp_sums[wid - 1] : 0) + carry_s;
        int excl = incl - v;
        if (i < n) { row_ptr[i] = excl; pos[i] = excl; }
        __syncthreads();
        if (threadIdx.x == 1023) carry_s = incl;
        __syncthreads();
    }
    if (threadIdx.x == 0) row_ptr[n] = carry_s;
}

__global__ void place_kernel(
    const int* __restrict__ src, const int* __restrict__ dst,
    const float* __restrict__ ew, int* __restrict__ pos,
    int2* __restrict__ edge_p, int E)
{
    int i = blockIdx.x * blockDim.x + threadIdx.x;
    if (i >= E) return;
    int p = atomicAdd(&pos[dst[i]], 1);
    edge_p[p] = make_int2(src[i], __float_as_int(ew[i]));
}

// ---------------------------------------------------------------------------
// mma.sync helpers
// ---------------------------------------------------------------------------
__device__ __forceinline__ uint32_t smem_u32(const void* p) {
    uint32_t a;
    asm("{ .reg .u64 t; cvta.to.shared.u64 t, %1; cvt.u32.u64 %0, t; }"
        : "=r"(a) : "l"(p));
    return a;
}

#define LDSM_X4(r0, r1, r2, r3, addr)                                         \
    asm volatile("ldmatrix.sync.aligned.m8n8.x4.shared.b16 {%0,%1,%2,%3}, [%4];" \
                 : "=r"(r0), "=r"(r1), "=r"(r2), "=r"(r3) : "r"(addr))

#define MMA_BF16(c, a, b)                                                     \
    asm volatile(                                                             \
        "mma.sync.aligned.m16n8k16.row.col.f32.bf16.bf16.f32 "                \
        "{%0,%1,%2,%3}, {%4,%5,%6,%7}, {%8,%9}, {%0,%1,%2,%3};"               \
        : "+f"((c)[0]), "+f"((c)[1]), "+f"((c)[2]), "+f"((c)[3])              \
        : "r"((a)[0]), "r"((a)[1]), "r"((a)[2]), "r"((a)[3]),                 \
          "r"((b)[0]), "r"((b)[1]))

// split (x, y) -> packed hi bf16x2, lo bf16x2 (element0 in low half)
__device__ __forceinline__ void split2(float x, float y, uint32_t& h, uint32_t& l) {
    __nv_bfloat16 hx = __float2bfloat16(x);
    __nv_bfloat16 hy = __float2bfloat16(y);
    __nv_bfloat16 lx = __float2bfloat16(x - __bfloat162float(hx));
    __nv_bfloat16 ly = __float2bfloat16(y - __bfloat162float(hy));
    h = ((uint32_t)__bfloat16_as_ushort(hy) << 16) | __bfloat16_as_ushort(hx);
    l = ((uint32_t)__bfloat16_as_ushort(ly) << 16) | __bfloat16_as_ushort(lx);
}

// ---------------------------------------------------------------------------
// Tensor-core GEMM: out[M, BN] = act(X[M,128]) @ W[128, BN]
// Block = 128 rows x BN cols, 512 threads = 16 warps (4m x 4n grid).
// A: [row][k] bf16 split tiles; W: transposed [n][k] bf16 split tiles
// (plain ldmatrix then yields the col-major B fragment).
// D = Ah*Bh + Ah*Bl + Al*Bh, fp32 accumulators. 8 k16-steps.
// ---------------------------------------------------------------------------
template <int BN, bool RELU>
__global__ void __launch_bounds__(512) gemm_mma_kernel(
    const float* __restrict__ X, const float* __restrict__ W,
    float* __restrict__ out, int M)
{
    constexpr int BM = 128;
    constexpr int SA = FEAT + 8;       // bf16 stride (16B-aligned rows)
    constexpr int NF = BN / 32;        // n-frags (8 cols) per warp: 4 or 2
    // smem (shorts): Ah | Al | Bth | Btl
    constexpr int OFF_AH = 0;
    constexpr int OFF_AL = OFF_AH + BM * SA;
    constexpr int OFF_BH = OFF_AL + BM * SA;
    constexpr int OFF_BL = OFF_BH + BN * SA;

    extern __shared__ unsigned short sm[];
    const int tid  = threadIdx.x;
    const int wid  = tid >> 5;
    const int lane = tid & 31;
    const int row0 = blockIdx.x * BM;

    // ---- Stage A: X rows -> split bf16 [row][k] ----
    for (int i = tid; i < BM * 16; i += 512) {
        int r = i >> 4;
        int g = i & 15;                // 8-element k group
        int grow = row0 + r;
        float4 va = make_float4(0.f, 0.f, 0.f, 0.f);
        float4 vb = make_float4(0.f, 0.f, 0.f, 0.f);
        if (grow < M) {
            va = *(const float4*)(X + (size_t)grow * FEAT + g * 8);
            vb = *(const float4*)(X + (size_t)grow * FEAT + g * 8 + 4);
            if (RELU) {
                va.x = fmaxf(va.x, 0.f); va.y = fmaxf(va.y, 0.f);
                va.z = fmaxf(va.z, 0.f); va.w = fmaxf(va.w, 0.f);
                vb.x = fmaxf(vb.x, 0.f); vb.y = fmaxf(vb.y, 0.f);
                vb.z = fmaxf(vb.z, 0.f); vb.w = fmaxf(vb.w, 0.f);
            }
        }
        uint4 hi, lo;
        split2(va.x, va.y, hi.x, lo.x);
        split2(va.z, va.w, hi.y, lo.y);
        split2(vb.x, vb.y, hi.z, lo.z);
        split2(vb.z, vb.w, hi.w, lo.w);
        *(uint4*)(sm + OFF_AH + r * SA + g * 8) = hi;
        *(uint4*)(sm + OFF_AL + r * SA + g * 8) = lo;
    }

    // ---- Stage B: W[k][n] -> split bf16 transposed [n][k] ----
    constexpr int N4 = BN / 4;
    for (int i = tid; i < FEAT * N4; i += 512) {
        int k  = i / N4;
        int n4 = (i % N4) * 4;
        float4 wv = *(const float4*)(W + (size_t)k * BN + n4);
#pragma unroll
        for (int j = 0; j < 4; j++) {
            float v = (&wv.x)[j];
            __nv_bfloat16 h = __float2bfloat16(v);
            __nv_bfloat16 l = __float2bfloat16(v - __bfloat162float(h));
            sm[OFF_BH + (n4 + j) * SA + k] = __bfloat16_as_ushort(h);
            sm[OFF_BL + (n4 + j) * SA + k] = __bfloat16_as_ushort(l);
        }
    }
    __syncthreads();

    const int warp_m = wid & 3;        // 4 m-groups x 32 rows
    const int warp_n = wid >> 2;       // 4 n-groups x NF*8 cols
    const uint32_t sb = smem_u32(sm);

    float c[2][NF][4];
#pragma unroll
    for (int mt = 0; mt < 2; mt++)
#pragma unroll
        for (int nf = 0; nf < NF; nf++)
#pragma unroll
            for (int q = 0; q < 4; q++) c[mt][nf][q] = 0.f;

    // A lane addressing: row = base + (lane&15), k = ks*16 + ((lane&16)>>1)
    const int a_row = warp_m * 32 + (lane & 15);
    const int a_kof = (lane & 16) >> 1;
    // B lane addressing: n = base + (lane&7) + ((lane&16)>>1), k = ks*16 + (lane&8)
    const int b_nof = (lane & 7) | ((lane & 16) >> 1);
    const int b_kof = lane & 8;

#pragma unroll
    for (int ks = 0; ks < 8; ks++) {
        const int kb = ks * 16;
        uint32_t ah[2][4], bh[NF][2];
        // Ah fragments (2 m-tiles)
#pragma unroll
        for (int mt = 0; mt < 2; mt++) {
            uint32_t ad = sb + (uint32_t)((OFF_AH) + (a_row + mt * 16) * SA + kb + a_kof) * 2u;
            LDSM_X4(ah[mt][0], ah[mt][1], ah[mt][2], ah[mt][3], ad);
        }
        // Bh fragments (NF n-tiles, x4 covers 2 at a time)
#pragma unroll
        for (int np = 0; np < NF / 2; np++) {
            int nb = warp_n * (NF * 8) + np * 16 + b_nof;
            uint32_t bd = sb + (uint32_t)((OFF_BH) + nb * SA + kb + b_kof) * 2u;
            LDSM_X4(bh[2 * np][0], bh[2 * np][1], bh[2 * np + 1][0], bh[2 * np + 1][1], bd);
        }
        // Ah * Bh
#pragma unroll
        for (int mt = 0; mt < 2; mt++)
#pragma unroll
            for (int nf = 0; nf < NF; nf++)
                MMA_BF16(c[mt][nf], ah[mt], bh[nf]);
        // Bl fragments, Ah * Bl
        {
            uint32_t bl[NF][2];
#pragma unroll
            for (int np = 0; np < NF / 2; np++) {
                int nb = warp_n * (NF * 8) + np * 16 + b_nof;
                uint32_t bd = sb + (uint32_t)((OFF_BL) + nb * SA + kb + b_kof) * 2u;
                LDSM_X4(bl[2 * np][0], bl[2 * np][1], bl[2 * np + 1][0], bl[2 * np + 1][1], bd);
            }
#pragma unroll
            for (int mt = 0; mt < 2; mt++)
#pragma unroll
                for (int nf = 0; nf < NF; nf++)
                    MMA_BF16(c[mt][nf], ah[mt], bl[nf]);
        }
        // Al fragments, Al * Bh
        {
            uint32_t al[2][4];
#pragma unroll
            for (int mt = 0; mt < 2; mt++) {
                uint32_t ad = sb + (uint32_t)((OFF_AL) + (a_row + mt * 16) * SA + kb + a_kof) * 2u;
                LDSM_X4(al[mt][0], al[mt][1], al[mt][2], al[mt][3], ad);
            }
#pragma unroll
            for (int mt = 0; mt < 2; mt++)
#pragma unroll
                for (int nf = 0; nf < NF; nf++)
                    MMA_BF16(c[mt][nf], al[mt], bh[nf]);
        }
    }

    // ---- Epilogue: write C fragments ----
    const int tq = lane >> 2;          // row within frag
    const int tr = lane & 3;           // col pair
#pragma unroll
    for (int mt = 0; mt < 2; mt++) {
#pragma unroll
        for (int nf = 0; nf < NF; nf++) {
            int col = warp_n * (NF * 8) + nf * 8 + tr * 2;
            int r1 = row0 + warp_m * 32 + mt * 16 + tq;
            if (r1 < M)
                *(float2*)(out + (size_t)r1 * BN + col) =
                    make_float2(c[mt][nf][0], c[mt][nf][1]);
            int r2 = r1 + 8;
            if (r2 < M)
                *(float2*)(out + (size_t)r2 * BN + col) =
                    make_float2(c[mt][nf][2], c[mt][nf][3]);
        }
    }
}

// ---------------------------------------------------------------------------
// Aggregate: one warp per dst node; acc = bias + sum_e w_e * support[src_e].
// (R10-measured config: 2 independent accumulators — at the chip LTS cap.)
// ---------------------------------------------------------------------------
template <int COLS>
__global__ void __launch_bounds__(256) aggregate_kernel(
    const float* __restrict__ support, const int* __restrict__ row_ptr,
    const int2* __restrict__ edge_p,
    const float* __restrict__ bias, float* __restrict__ out, int M)
{
    int warp = (blockIdx.x * blockDim.x + threadIdx.x) >> 5;
    int lane = threadIdx.x & 31;
    if (warp >= M) return;

    const int beg = row_ptr[warp];
    const int end = row_ptr[warp + 1];

    if (COLS == 128) {
        float4 acc0 = ((const float4*)bias)[lane];
        float4 acc1 = make_float4(0.f, 0.f, 0.f, 0.f);
        for (int e = beg; e < end; e += 32) {
            int n = min(32, end - e);
            int s = 0, wbits = 0;
            if (lane < n) {
                int2 m = __ldg(edge_p + e + lane);
                s = m.x; wbits = m.y;
            }
            int j = 0;
#pragma unroll 2
            for (; j + 1 < n; j += 2) {
                int   s0 = __shfl_sync(0xffffffffu, s, j);
                float w0 = __int_as_float(__shfl_sync(0xffffffffu, wbits, j));
                int   s1 = __shfl_sync(0xffffffffu, s, j + 1);
                float w1 = __int_as_float(__shfl_sync(0xffffffffu, wbits, j + 1));
                float4 v0 = ((const float4*)(support + (size_t)s0 * 128))[lane];
                float4 v1 = ((const float4*)(support + (size_t)s1 * 128))[lane];
                acc0.x += w0 * v0.x; acc0.y += w0 * v0.y;
                acc0.z += w0 * v0.z; acc0.w += w0 * v0.w;
                acc1.x += w1 * v1.x; acc1.y += w1 * v1.y;
                acc1.z += w1 * v1.z; acc1.w += w1 * v1.w;
            }
            if (j < n) {
                int   sj = __shfl_sync(0xffffffffu, s, j);
                float wj = __int_as_float(__shfl_sync(0xffffffffu, wbits, j));
                float4 v = ((const float4*)(support + (size_t)sj * 128))[lane];
                acc0.x += wj * v.x; acc0.y += wj * v.y;
                acc0.z += wj * v.z; acc0.w += wj * v.w;
            }
        }
        acc0.x += acc1.x; acc0.y += acc1.y; acc0.z += acc1.z; acc0.w += acc1.w;
        ((float4*)(out + (size_t)warp * 128))[lane] = acc0;
    } else {  // COLS == 64
        float2 acc0 = ((const float2*)bias)[lane];
        float2 acc1 = make_float2(0.f, 0.f);
        for (int e = beg; e < end; e += 32) {
            int n = min(32, end - e);
            int s = 0, wbits = 0;
            if (lane < n) {
                int2 m = __ldg(edge_p + e + lane);
                s = m.x; wbits = m.y;
            }
            int j = 0;
#pragma unroll 2
            for (; j + 1 < n; j += 2) {
                int   s0 = __shfl_sync(0xffffffffu, s, j);
                float w0 = __int_as_float(__shfl_sync(0xffffffffu, wbits, j));
                int   s1 = __shfl_sync(0xffffffffu, s, j + 1);
                float w1 = __int_as_float(__shfl_sync(0xffffffffu, wbits, j + 1));
                float2 v0 = ((const float2*)(support + (size_t)s0 * 64))[lane];
                float2 v1 = ((const float2*)(support + (size_t)s1 * 64))[lane];
                acc0.x += w0 * v0.x; acc0.y += w0 * v0.y;
                acc1.x += w1 * v1.x; acc1.y += w1 * v1.y;
            }
            if (j < n) {
                int   sj = __shfl_sync(0xffffffffu, s, j);
                float wj = __int_as_float(__shfl_sync(0xffffffffu, wbits, j));
                float2 v = ((const float2*)(support + (size_t)sj * 64))[lane];
                acc0.x += wj * v.x; acc0.y += wj * v.y;
            }
        }
        acc0.x += acc1.x; acc0.y += acc1.y;
        ((float2*)(out + (size_t)warp * 64))[lane] = acc0;
    }
}

// ---------------------------------------------------------------------------
// Launch
// ---------------------------------------------------------------------------
static inline int cdiv(int a, int b) { return (a + b - 1) / b; }

extern "C" void kernel_launch(void* const* d_in, const int* in_sizes, int n_in,
                              void* d_out, int out_size)
{
    const float* x    = (const float*)d_in[0];
    const int*   esrc = (const int*)  d_in[1];
    const int*   edst = (const int*)  d_in[2];
    const float* ew   = (const float*)d_in[3];
    const float* W0   = (const float*)d_in[4];
    const float* b0   = (const float*)d_in[5];
    const float* W1   = (const float*)d_in[6];
    const float* b1   = (const float*)d_in[7];
    const float* W2   = (const float*)d_in[8];
    const float* b2   = (const float*)d_in[9];
    const float* W3   = (const float*)d_in[10];
    const float* b3   = (const float*)d_in[11];
    float*       out  = (float*)d_out;

    const int M = in_sizes[0] / FEAT;   // 50000
    const int E = in_sizes[1];          // 800000

    float *bufA, *bufB;
    int *counts, *rowptr, *pos;
    int2 *edge_p;
    cudaGetSymbolAddress((void**)&bufA,   g_bufA);
    cudaGetSymbolAddress((void**)&bufB,   g_bufB);
    cudaGetSymbolAddress((void**)&counts, g_counts);
    cudaGetSymbolAddress((void**)&rowptr, g_rowptr);
    cudaGetSymbolAddress((void**)&pos,    g_pos);
    cudaGetSymbolAddress((void**)&edge_p, g_edge_p);

    // smem shorts: (2*BM + 2*BN) * (FEAT+8) * 2 bytes
    const int smem128 = (2 * 128 + 2 * 128) * (FEAT + 8) * 2;  // 139264
    const int smem64  = (2 * 128 + 2 * 64)  * (FEAT + 8) * 2;  // 104448
    cudaFuncSetAttribute(gemm_mma_kernel<128, false>,
                         cudaFuncAttributeMaxDynamicSharedMemorySize, smem128);
    cudaFuncSetAttribute(gemm_mma_kernel<128, true>,
                         cudaFuncAttributeMaxDynamicSharedMemorySize, smem128);
    cudaFuncSetAttribute(gemm_mma_kernel<64, true>,
                         cudaFuncAttributeMaxDynamicSharedMemorySize, smem64);

    const int gemm_blocks = cdiv(M, 128);       // 391
    const int agg_blocks  = cdiv(M * 32, 256);
    const int e_blocks    = cdiv(E, 256);

    // ---- CSR build (once; reused by all 4 layers) ----
    cudaMemsetAsync(counts, 0, M * sizeof(int));
    hist_kernel<<<e_blocks, 256>>>(edst, counts, E);
    scan_kernel<<<1, 1024>>>(counts, rowptr, pos, M);
    place_kernel<<<e_blocks, 256>>>(esrc, edst, ew, pos, edge_p, E);

    // ---- Layer 0 ----
    gemm_mma_kernel<128, false><<<gemm_blocks, 512, smem128>>>(x, W0, bufB, M);
    aggregate_kernel<128><<<agg_blocks, 256>>>(bufB, rowptr, edge_p, b0, bufA, M);

    // ---- Layer 1 ----
    gemm_mma_kernel<128, true><<<gemm_blocks, 512, smem128>>>(bufA, W1, bufB, M);
    aggregate_kernel<128><<<agg_blocks, 256>>>(bufB, rowptr, edge_p, b1, bufA, M);

    // ---- Layer 2 ----
    gemm_mma_kernel<128, true><<<gemm_blocks, 512, smem128>>>(bufA, W2, bufB, M);
    aggregate_kernel<128><<<agg_blocks, 256>>>(bufB, rowptr, edge_p, b2, bufA, M);

    // ---- Layer 3 (NOUT=64, no relu on output) ----
    gemm_mma_kernel<64, true><<<gemm_blocks, 512, smem64>>>(bufA, W3, bufB, M);
    aggregate_kernel<64><<<agg_blocks, 256>>>(bufB, rowptr, edge_p, b3, out, M);
}